// round 14
// baseline (speedup 1.0000x reference)
#include <cuda_runtime.h>
#include <cuda_bf16.h>

// ---------------------------------------------------------------------------
// MLP_TI_Gram: y = MLP(mean-of-shifted-diagonal of per-batch Gram matrix)
// diag-mean == circular autocorrelation == FFT(sum_d |FFT(x_d)|^2)/N^2
// (Wiener-Khinchin). B=128, N=1024, H=128.
// fftcorr: ONE CTA PER BATCH PAIR (64 CTAs x 1024 thr): forward = 4 signals
// in decoupled 256-thread barrier domains; inverse = ONE packed FFT
// (u = P_b0 + i*P_b1; both real-even => Re->c_b0, Im->c_b1).
// Pipeline: fftcorr -> gemm1 (PDL) -> mlp23 (PDL).
// ---------------------------------------------------------------------------

#define BATCH 128
#define NSEQ  1024
#define HID   128

typedef unsigned long long u64;

__device__ float g_c[BATCH * NSEQ];    // correlation (scratch)
__device__ float g_h1[BATCH * HID];    // layer-1 activations (scratch)

// ---- f32x2 packed helpers (Blackwell, PTX-only) ---------------------------
__device__ __forceinline__ u64 pk2(float lo, float hi) {
    u64 r;
    asm("mov.b64 %0, {%1,%2};" : "=l"(r) : "f"(lo), "f"(hi));
    return r;
}
__device__ __forceinline__ void upk2(u64 v, float& lo, float& hi) {
    asm("mov.b64 {%0,%1}, %2;" : "=f"(lo), "=f"(hi) : "l"(v));
}
__device__ __forceinline__ u64 fma2(u64 a, u64 b, u64 c) {
    u64 d;
    asm("fma.rn.f32x2 %0, %1, %2, %3;" : "=l"(d) : "l"(a), "l"(b), "l"(c));
    return d;
}
__device__ __forceinline__ u64 add2(u64 a, u64 b) {
    u64 d;
    asm("add.rn.f32x2 %0, %1, %2;" : "=l"(d) : "l"(a), "l"(b));
    return d;
}

__device__ __forceinline__ float celu1(float v) {
    return v > 0.0f ? v : expm1f(v);
}
__device__ __forceinline__ float2 cmul(float2 a, float2 b) {
    return make_float2(a.x * b.x - a.y * b.y, a.x * b.y + a.y * b.x);
}

// named barrier: id, thread count (whole warps)
__device__ __forceinline__ void barx(int id, int cnt) {
    asm volatile("bar.sync %0, %1;" :: "r"(id), "r"(cnt) : "memory");
}

// ---- PDL primitives --------------------------------------------------------
__device__ __forceinline__ void pdl_wait() {
    asm volatile("griddepcontrol.wait;" ::: "memory");
}
__device__ __forceinline__ void pdl_trigger() {
    asm volatile("griddepcontrol.launch_dependents;" ::: "memory");
}

// ---------------------------------------------------------------------------
// Kernel 1: correlation via FFT. 64 CTAs (one per batch pair), 1024 threads.
// Group g = t>>8 owns signal g: (batch blockIdx.x*2 + (g>>1), kind g&1)
// where kind 0 = ch0 + i*ch1, kind 1 = ch2 + 0i. Named barrier 1+g.
// Inverse (group 0, 256 thr): u = P_b0 + i*P_b1, one 1024-pt FFT; the output
// real/imag parts are N^2*c_b0 / N^2*c_b1.
// Dynamic smem: bufA[4][1024] f2 | bufB[4][1024] f2 | twg[4][256] f2 = 72KB.
// ---------------------------------------------------------------------------
#define FFT_SMEM ((4 * 1024 + 4 * 1024 + 4 * 256) * 8)

__global__ __launch_bounds__(1024, 1)
void fftcorr_kernel(const float* __restrict__ x) {
    extern __shared__ float2 fsm[];
    float2* bufA = fsm;                 // [4][1024]
    float2* bufB = fsm + 4096;          // [4][1024]
    float2* twg  = fsm + 8192;          // [4][256]

    const int t = threadIdx.x;
    const int g = t >> 8;               // signal group 0..3
    const int i = t & 255;              // butterfly index within group

    const int bb = blockIdx.x * 2 + (g >> 1);   // batch for this group
    const int kind = g & 1;                      // 0: ch01, 1: ch2

    float2* mA = bufA + g * 1024;       // group-private buffers
    float2* mB = bufB + g * 1024;
    float2* tw = twg + g * 256;         // group-private twiddle table

    // twiddle: tw[m] = exp(-2*pi*i*m/1024), m < 256
    {
        float s_, c_;
        sincospif(-(float)i * (1.0f / 512.0f), &s_, &c_);
        tw[i] = make_float2(c_, s_);
    }

    const float* __restrict__ xb = x + (size_t)bb * NSEQ * 3;

    // ---- forward stage 0 (s=0, w=1): load x directly from gmem ----
    {
        float2 a0, a1, a2, a3;
        if (kind == 0) {
            a0 = make_float2(xb[3 * i],           xb[3 * i + 1]);
            a1 = make_float2(xb[3 * (i + 256)],   xb[3 * (i + 256) + 1]);
            a2 = make_float2(xb[3 * (i + 512)],   xb[3 * (i + 512) + 1]);
            a3 = make_float2(xb[3 * (i + 768)],   xb[3 * (i + 768) + 1]);
        } else {
            a0 = make_float2(xb[3 * i + 2],         0.0f);
            a1 = make_float2(xb[3 * (i + 256) + 2], 0.0f);
            a2 = make_float2(xb[3 * (i + 512) + 2], 0.0f);
            a3 = make_float2(xb[3 * (i + 768) + 2], 0.0f);
        }
        float2 t02p = make_float2(a0.x + a2.x, a0.y + a2.y);
        float2 t02m = make_float2(a0.x - a2.x, a0.y - a2.y);
        float2 t13p = make_float2(a1.x + a3.x, a1.y + a3.y);
        float2 t13m = make_float2(a1.x - a3.x, a1.y - a3.y);
        const int d = i << 2;
        mA[d]     = make_float2(t02p.x + t13p.x, t02p.y + t13p.y);
        mA[d + 1] = make_float2(t02m.x + t13m.y, t02m.y - t13m.x);
        mA[d + 2] = make_float2(t02p.x - t13p.x, t02p.y - t13p.y);
        mA[d + 3] = make_float2(t02m.x - t13m.y, t02m.y + t13m.x);
    }
    barx(1 + g, 256);   // group-local join (also covers tw init)

    // ---- forward stages 1..3 (group-local barriers) ----
    {
        float2* src = mA;
        float2* dst = mB;
#pragma unroll
        for (int s = 1; s < 4; s++) {
            const int L = 1 << (2 * s);
            const int q = i & (L - 1);
            const int d = ((i >> (2 * s)) << (2 * s + 2)) | q;
            const float2 w1t = tw[q << (8 - 2 * s)];
            const float2 w2t = make_float2(w1t.x * w1t.x - w1t.y * w1t.y,
                                           2.0f * w1t.x * w1t.y);
            const float2 w3t = cmul(w2t, w1t);

            float2 a0 = src[i];
            float2 a1 = src[i + 256];
            float2 a2 = src[i + 512];
            float2 a3 = src[i + 768];
            float2 b1 = cmul(a1, w1t);
            float2 b2 = cmul(a2, w2t);
            float2 b3 = cmul(a3, w3t);

            float2 t02p = make_float2(a0.x + b2.x, a0.y + b2.y);
            float2 t02m = make_float2(a0.x - b2.x, a0.y - b2.y);
            float2 t13p = make_float2(b1.x + b3.x, b1.y + b3.y);
            float2 t13m = make_float2(b1.x - b3.x, b1.y - b3.y);

            dst[d]         = make_float2(t02p.x + t13p.x, t02p.y + t13p.y);
            dst[d + L]     = make_float2(t02m.x + t13m.y, t02m.y - t13m.x);
            dst[d + 2 * L] = make_float2(t02p.x - t13p.x, t02p.y - t13p.y);
            dst[d + 3 * L] = make_float2(t02m.x - t13m.y, t02m.y + t13m.x);

            float2* tmp = src; src = dst; dst = tmp;
            barx(1 + g, 256);
        }
    }
    // 3 passes: A->B->A->B  => stage-3 output in mB

    // ---- forward stage 4 (last): write spectra into mA, then FULL join ----
    {
        const float2 w1t = tw[i];        // q = i, L = 256, d = i
        const float2 w2t = make_float2(w1t.x * w1t.x - w1t.y * w1t.y,
                                       2.0f * w1t.x * w1t.y);
        const float2 w3t = cmul(w2t, w1t);

        float2 a0 = mB[i];
        float2 a1 = mB[i + 256];
        float2 a2 = mB[i + 512];
        float2 a3 = mB[i + 768];
        float2 b1 = cmul(a1, w1t);
        float2 b2 = cmul(a2, w2t);
        float2 b3 = cmul(a3, w3t);

        float2 t02p = make_float2(a0.x + b2.x, a0.y + b2.y);
        float2 t02m = make_float2(a0.x - b2.x, a0.y - b2.y);
        float2 t13p = make_float2(b1.x + b3.x, b1.y + b3.y);
        float2 t13m = make_float2(b1.x - b3.x, b1.y - b3.y);

        mA[i]       = make_float2(t02p.x + t13p.x, t02p.y + t13p.y);
        mA[i + 256] = make_float2(t02m.x + t13m.y, t02m.y - t13m.x);
        mA[i + 512] = make_float2(t02p.x - t13p.x, t02p.y - t13p.y);
        mA[i + 768] = make_float2(t02m.x - t13m.y, t02m.y + t13m.x);
    }
    __syncthreads();   // full join: 4 spectra in bufA[0..3]

    // ---- inverse on group 0: u = P_b0 + i*P_b1, stage 0 fused with PS ----
    if (t < 256) {
        const float2* Z01a = bufA;            // batch b0: ch01 spectrum
        const float2* Z2a  = bufA + 1024;     // batch b0: ch2 spectrum
        const float2* Z01b = bufA + 2048;     // batch b1: ch01 spectrum
        const float2* Z2b  = bufA + 3072;     // batch b1: ch2 spectrum

        float2 u[4];
#pragma unroll
        for (int r = 0; r < 4; r++) {
            int k = t + 256 * r;
            int m = (1024 - k) & 1023;
            float2 za  = Z01a[k], zam = Z01a[m], z2a = Z2a[k];
            float2 zb  = Z01b[k], zbm = Z01b[m], z2b = Z2b[k];
            float P0 = 0.5f * (za.x * za.x + za.y * za.y +
                               zam.x * zam.x + zam.y * zam.y)
                     + (z2a.x * z2a.x + z2a.y * z2a.y);
            float P1 = 0.5f * (zb.x * zb.x + zb.y * zb.y +
                               zbm.x * zbm.x + zbm.y * zbm.y)
                     + (z2b.x * z2b.x + z2b.y * z2b.y);
            u[r] = make_float2(P0, P1);
        }
        // general complex radix-4 butterfly (w = 1)
        float2 t02p = make_float2(u[0].x + u[2].x, u[0].y + u[2].y);
        float2 t02m = make_float2(u[0].x - u[2].x, u[0].y - u[2].y);
        float2 t13p = make_float2(u[1].x + u[3].x, u[1].y + u[3].y);
        float2 t13m = make_float2(u[1].x - u[3].x, u[1].y - u[3].y);
        const int d = t << 2;
        bufB[d]     = make_float2(t02p.x + t13p.x, t02p.y + t13p.y);
        bufB[d + 1] = make_float2(t02m.x + t13m.y, t02m.y - t13m.x);
        bufB[d + 2] = make_float2(t02p.x - t13p.x, t02p.y - t13p.y);
        bufB[d + 3] = make_float2(t02m.x - t13m.y, t02m.y + t13m.x);

        barx(1, 256);

        // ---- inverse stages 1..3 ----
        const float2* tw0 = twg;    // group 0 table
        float2* src = bufB;
        float2* dst = bufA;
#pragma unroll
        for (int s = 1; s < 4; s++) {
            const int L = 1 << (2 * s);
            const int q = t & (L - 1);
            const int d2 = ((t >> (2 * s)) << (2 * s + 2)) | q;
            const float2 w1t = tw0[q << (8 - 2 * s)];
            const float2 w2t = make_float2(w1t.x * w1t.x - w1t.y * w1t.y,
                                           2.0f * w1t.x * w1t.y);
            const float2 w3t = cmul(w2t, w1t);

            float2 a0 = src[t];
            float2 a1 = src[t + 256];
            float2 a2 = src[t + 512];
            float2 a3 = src[t + 768];
            float2 b1 = cmul(a1, w1t);
            float2 b2 = cmul(a2, w2t);
            float2 b3 = cmul(a3, w3t);

            float2 t02p2 = make_float2(a0.x + b2.x, a0.y + b2.y);
            float2 t02m2 = make_float2(a0.x - b2.x, a0.y - b2.y);
            float2 t13p2 = make_float2(b1.x + b3.x, b1.y + b3.y);
            float2 t13m2 = make_float2(b1.x - b3.x, b1.y - b3.y);

            dst[d2]         = make_float2(t02p2.x + t13p2.x, t02p2.y + t13p2.y);
            dst[d2 + L]     = make_float2(t02m2.x + t13m2.y, t02m2.y - t13m2.x);
            dst[d2 + 2 * L] = make_float2(t02p2.x - t13p2.x, t02p2.y - t13p2.y);
            dst[d2 + 3 * L] = make_float2(t02m2.x - t13m2.y, t02m2.y + t13m2.x);

            float2* tmp = src; src = dst; dst = tmp;
            barx(1, 256);
        }
        // 3 passes: B->A->B->A  => stage-3 output in bufA

        // ---- inverse stage 4: fused scaled store (Re->c_b0, Im->c_b1) ----
        {
            const float2 w1t = tw0[t];     // q = t, L = 256
            const float2 w2t = make_float2(w1t.x * w1t.x - w1t.y * w1t.y,
                                           2.0f * w1t.x * w1t.y);
            const float2 w3t = cmul(w2t, w1t);

            float2 a0 = bufA[t];
            float2 a1 = bufA[t + 256];
            float2 a2 = bufA[t + 512];
            float2 a3 = bufA[t + 768];
            float2 b1 = cmul(a1, w1t);
            float2 b2 = cmul(a2, w2t);
            float2 b3 = cmul(a3, w3t);

            float2 t02p2 = make_float2(a0.x + b2.x, a0.y + b2.y);
            float2 t02m2 = make_float2(a0.x - b2.x, a0.y - b2.y);
            float2 t13p2 = make_float2(b1.x + b3.x, b1.y + b3.y);
            float2 t13m2 = make_float2(b1.x - b3.x, b1.y - b3.y);

            float2 o0 = make_float2(t02p2.x + t13p2.x, t02p2.y + t13p2.y);
            float2 o1 = make_float2(t02m2.x + t13m2.y, t02m2.y - t13m2.x);
            float2 o2 = make_float2(t02p2.x - t13p2.x, t02p2.y - t13p2.y);
            float2 o3 = make_float2(t02m2.x - t13m2.y, t02m2.y + t13m2.x);

            const float inv = 1.0f / (1024.0f * 1024.0f);
            const int b0 = blockIdx.x * 2;
            float* __restrict__ c0 = g_c + (size_t)b0 * NSEQ;
            float* __restrict__ c1 = g_c + (size_t)(b0 + 1) * NSEQ;
            c0[t]       = o0.x * inv;  c1[t]       = o0.y * inv;
            c0[t + 256] = o1.x * inv;  c1[t + 256] = o1.y * inv;
            c0[t + 512] = o2.x * inv;  c1[t + 512] = o2.y * inv;
            c0[t + 768] = o3.x * inv;  c1[t + 768] = o3.y * inv;
        }
    }

    __threadfence();
    __syncthreads();
    pdl_trigger();
}

// ---------------------------------------------------------------------------
// Kernel 2: tiled layer-1 GEMM (PDL consumer). W1 staged pre-wait.
// Grid 128 = 16 batch-tiles (8 batches) x 8 h-tiles (16 h). 512 threads.
// ---------------------------------------------------------------------------
#define CSH_PITCH 1025
#define RED_PITCH 66
#define GEMM1_SMEM ((4 * CSH_PITCH + 1024 * 16 + 32 * RED_PITCH) * 8)

__global__ __launch_bounds__(512, 1)
void gemm1_kernel(const float* __restrict__ W1, const float* __restrict__ b1) {
    extern __shared__ char dsm[];
    u64 (*csh)[CSH_PITCH] = (u64(*)[CSH_PITCH])dsm;
    u64 (*w1d)[16]        = (u64(*)[16])(dsm + 4 * CSH_PITCH * 8);
    u64 (*red)[RED_PITCH] = (u64(*)[RED_PITCH])(dsm + (4 * CSH_PITCH + 1024 * 16) * 8);

    const int t  = threadIdx.x;
    const int bt = blockIdx.x >> 3;
    const int ht = blockIdx.x & 7;
    const int b0 = bt * 8;
    const int H0 = ht * 16;

    // pre-wait prologue: stage W1 slice (independent of fft output)
#pragma unroll
    for (int it = 0; it < 8; it++) {
        int idx = t + it * 512;
        int j = idx >> 2, hq = idx & 3;
        float4 wv = *(const float4*)&W1[j * HID + H0 + hq * 4];
        ulonglong2* dst = (ulonglong2*)&w1d[j][hq * 4];
        dst[0] = make_ulonglong2(pk2(wv.x, wv.x), pk2(wv.y, wv.y));
        dst[1] = make_ulonglong2(pk2(wv.z, wv.z), pk2(wv.w, wv.w));
    }

    pdl_wait();

#pragma unroll
    for (int it = 0; it < 8; it++) {
        int idx = t + it * 512;
        int bp_ = idx >> 10, j = idx & 1023;
        csh[bp_][j] = pk2(g_c[(b0 + 2 * bp_) * NSEQ + j],
                          g_c[(b0 + 2 * bp_ + 1) * NSEQ + j]);
    }
    __syncthreads();

    const int bp = t & 3;
    const int h4 = (t >> 2) & 3;
    const int jq = t >> 4;
    const int j0 = jq * 32;

    u64 a0 = 0ull, a1 = 0ull, a2 = 0ull, a3 = 0ull;
#pragma unroll 8
    for (int j = j0; j < j0 + 32; j++) {
        u64 cv = csh[bp][j];
        const ulonglong2* wr = (const ulonglong2*)&w1d[j][h4 * 4];
        ulonglong2 w01 = wr[0];
        ulonglong2 w23 = wr[1];
        a0 = fma2(cv, w01.x, a0);
        a1 = fma2(cv, w01.y, a1);
        a2 = fma2(cv, w23.x, a2);
        a3 = fma2(cv, w23.y, a3);
    }
    {
        ulonglong2* rr = (ulonglong2*)&red[jq][bp * 16 + h4 * 4];
        rr[0] = make_ulonglong2(a0, a1);
        rr[1] = make_ulonglong2(a2, a3);
    }
    __syncthreads();

    if (t < 64) {
        int bp_ = t >> 4, h = t & 15;
        int cell = bp_ * 16 + h;
        u64 s0 = 0ull, s1 = 0ull, s2 = 0ull, s3 = 0ull;
#pragma unroll
        for (int q = 0; q < 32; q += 4) {
            s0 = add2(s0, red[q + 0][cell]);
            s1 = add2(s1, red[q + 1][cell]);
            s2 = add2(s2, red[q + 2][cell]);
            s3 = add2(s3, red[q + 3][cell]);
        }
        u64 s = add2(add2(s0, s1), add2(s2, s3));
        float va, vb;
        upk2(s, va, vb);
        float bb = b1[H0 + h];
        g_h1[(b0 + 2 * bp_) * HID + H0 + h]     = celu1(va + bb);
        g_h1[(b0 + 2 * bp_ + 1) * HID + H0 + h] = celu1(vb + bb);
        __threadfence();
    }
    __syncthreads();
    pdl_trigger();
}

// ---------------------------------------------------------------------------
// Kernel 3: layers 2+3 (PDL consumer). Weights staged pre-wait.
// 128 blocks, 256 threads.
// ---------------------------------------------------------------------------
#define MLP23_SMEM ((16384 + 128 + 128 + 512 + 128) * 4)

__global__ __launch_bounds__(256, 1)
void mlp23_kernel(const float* __restrict__ W2, const float* __restrict__ b2,
                  const float* __restrict__ W3, const float* __restrict__ b3,
                  float* __restrict__ out) {
    extern __shared__ float msm[];
    float* w2s = msm;               // [128*128]
    float* b2s = msm + 16384;       // [128]
    float* w3s = msm + 16512;       // [128]
    float* s2  = msm + 16640;       // [4][128]
    float* h1s = msm + 17152;       // [128]

    const int b = blockIdx.x, t = threadIdx.x;

    {   // pre-wait prologue: stage all weights
        const float4* __restrict__ W2v = (const float4*)W2;
        float4* w2sv = (float4*)w2s;
#pragma unroll
        for (int i = 0; i < 16; i++) w2sv[t + i * 256] = W2v[t + i * 256];
        if (t < 128) {
            b2s[t] = b2[t];
            w3s[t] = W3[t];
        }
    }

    pdl_wait();

    if (t < HID) h1s[t] = g_h1[b * HID + t];
    __syncthreads();

    const int kh = t >> 7, h = t & (HID - 1);
    const int k0 = kh * 64;
    float acc0 = 0.f, acc1 = 0.f, acc2 = 0.f, acc3 = 0.f;
#pragma unroll
    for (int k = k0; k < k0 + 64; k += 4) {
        acc0 += h1s[k + 0] * w2s[(k + 0) * HID + h];
        acc1 += h1s[k + 1] * w2s[(k + 1) * HID + h];
        acc2 += h1s[k + 2] * w2s[(k + 2) * HID + h];
        acc3 += h1s[k + 3] * w2s[(k + 3) * HID + h];
    }
    s2[kh * 128 + h] = (acc0 + acc1) + (acc2 + acc3);
    __syncthreads();

    if (t < HID) {
        float v = s2[t] + s2[128 + t] + b2s[t];
        s2[t] = celu1(v) * w3s[t];
    }
    __syncthreads();
#pragma unroll
    for (int o = 64; o > 0; o >>= 1) {
        if (t < o) s2[t] += s2[t + o];
        __syncthreads();
    }
    if (t == 0) out[b] = s2[0] + b3[0];
}

// ---------------------------------------------------------------------------
extern "C" void kernel_launch(void* const* d_in, const int* in_sizes, int n_in,
                              void* d_out, int out_size) {
    const float* x  = (const float*)d_in[0];
    const float* W1 = (const float*)d_in[1];
    const float* b1 = (const float*)d_in[2];
    const float* W2 = (const float*)d_in[3];
    const float* b2 = (const float*)d_in[4];
    const float* W3 = (const float*)d_in[5];
    const float* b3 = (const float*)d_in[6];
    float* out = (float*)d_out;

    static int configured = 0;
    if (!configured) {
        cudaFuncSetAttribute(fftcorr_kernel,
                             cudaFuncAttributeMaxDynamicSharedMemorySize,
                             FFT_SMEM);
        cudaFuncSetAttribute(gemm1_kernel,
                             cudaFuncAttributeMaxDynamicSharedMemorySize,
                             GEMM1_SMEM);
        cudaFuncSetAttribute(mlp23_kernel,
                             cudaFuncAttributeMaxDynamicSharedMemorySize,
                             MLP23_SMEM);
        configured = 1;
    }

    fftcorr_kernel<<<BATCH / 2, 1024, FFT_SMEM>>>(x);

    cudaLaunchAttribute attrs[1];
    attrs[0].id = cudaLaunchAttributeProgrammaticStreamSerialization;
    attrs[0].val.programmaticStreamSerializationAllowed = 1;

    {   // gemm1 with PDL
        cudaLaunchConfig_t cfg = {};
        cfg.gridDim = dim3(128, 1, 1);
        cfg.blockDim = dim3(512, 1, 1);
        cfg.dynamicSmemBytes = GEMM1_SMEM;
        cfg.attrs = attrs;
        cfg.numAttrs = 1;
        cudaLaunchKernelEx(&cfg, gemm1_kernel, W1, b1);
    }
    {   // mlp23 with PDL
        cudaLaunchConfig_t cfg = {};
        cfg.gridDim = dim3(BATCH, 1, 1);
        cfg.blockDim = dim3(256, 1, 1);
        cfg.dynamicSmemBytes = MLP23_SMEM;
        cfg.attrs = attrs;
        cfg.numAttrs = 1;
        cudaLaunchKernelEx(&cfg, mlp23_kernel, W2, b2, W3, b3, out);
    }
}

// round 15
// speedup vs baseline: 1.1401x; 1.1401x over previous
#include <cuda_runtime.h>
#include <cuda_bf16.h>

// ---------------------------------------------------------------------------
// MLP_TI_Gram, fully self-contained single kernel. 64 CTAs x 1024 threads,
// one batch PAIR per CTA, zero cross-CTA communication.
//   phase 1: 4 forward 1024-pt FFTs (b0.ch01, b0.ch2, b1.ch01, b1.ch2) in
//            decoupled 256-thread named-barrier domains (radix-4 Stockham).
//   phase 2: packed inverse  u = P_b0 + i*P_b1  ->  Re = c_b0, Im = c_b1,
//            kept in shared memory (never hits gmem).
//   phase 3: gemm1  h1[b] = celu(c[b] @ W1 + b1)   (W1 streamed from L2).
//   phase 4: mlp23  y[b] = celu(h1@W2+b2) @ W3 + b3  ->  out.
// ---------------------------------------------------------------------------

#define BATCH 128
#define NSEQ  1024
#define HID   128

typedef unsigned long long u64;

// ---- f32x2 packed helpers (Blackwell, PTX-only) ---------------------------
__device__ __forceinline__ u64 pk2(float lo, float hi) {
    u64 r;
    asm("mov.b64 %0, {%1,%2};" : "=l"(r) : "f"(lo), "f"(hi));
    return r;
}
__device__ __forceinline__ void upk2(u64 v, float& lo, float& hi) {
    asm("mov.b64 {%0,%1}, %2;" : "=f"(lo), "=f"(hi) : "l"(v));
}
__device__ __forceinline__ u64 fma2(u64 a, u64 b, u64 c) {
    u64 d;
    asm("fma.rn.f32x2 %0, %1, %2, %3;" : "=l"(d) : "l"(a), "l"(b), "l"(c));
    return d;
}
__device__ __forceinline__ u64 add2(u64 a, u64 b) {
    u64 d;
    asm("add.rn.f32x2 %0, %1, %2;" : "=l"(d) : "l"(a), "l"(b));
    return d;
}

__device__ __forceinline__ float celu1(float v) {
    return v > 0.0f ? v : expm1f(v);
}
__device__ __forceinline__ float2 cmul(float2 a, float2 b) {
    return make_float2(a.x * b.x - a.y * b.y, a.x * b.y + a.y * b.x);
}
__device__ __forceinline__ void barx(int id, int cnt) {
    asm volatile("bar.sync %0, %1;" :: "r"(id), "r"(cnt) : "memory");
}

// ---------------------------------------------------------------------------
// Dynamic smem layout (72KB + 10KB tail scratch kept inside same 72KB via
// overlays):
//   [0      .. 32768)  bufA   float2[4][1024]      | overlay: part u64[32][128]
//   [32768  .. 65536)  bufB   float2[4][1024]      | overlay: c2 u64[1024] (first
//                                                   8KB), s2 u64[8][128] (next 8KB),
//                                                   rb u64[128] (next 1KB)
//   [65536  .. 73728)  twg    float2[4][256]       | overlay: red2 u64[4][128],
//                                                   h1s float[2][128]
// ---------------------------------------------------------------------------
#define SMEM_BYTES 73728

__global__ __launch_bounds__(1024, 1)
void fused_all(const float* __restrict__ x,
               const float* __restrict__ W1, const float* __restrict__ b1,
               const float* __restrict__ W2, const float* __restrict__ b2,
               const float* __restrict__ W3, const float* __restrict__ b3,
               float* __restrict__ out) {
    extern __shared__ char dsm[];
    float2* bufA = (float2*)dsm;              // [4][1024]
    float2* bufB = (float2*)(dsm + 32768);    // [4][1024]
    float2* twg  = (float2*)(dsm + 65536);    // [4][256]

    const int t = threadIdx.x;
    const int g = t >> 8;               // signal group 0..3
    const int i = t & 255;

    const int B0 = blockIdx.x * 2;
    const int bb = B0 + (g >> 1);       // batch for this group
    const int kind = g & 1;             // 0: ch0+i*ch1, 1: ch2+0i

    float2* mA = bufA + g * 1024;
    float2* mB = bufB + g * 1024;
    float2* tw = twg + g * 256;

    // twiddle: tw[m] = exp(-2*pi*i*m/1024)
    {
        float s_, c_;
        sincospif(-(float)i * (1.0f / 512.0f), &s_, &c_);
        tw[i] = make_float2(c_, s_);
    }

    const float* __restrict__ xb = x + (size_t)bb * NSEQ * 3;

    // ---- forward stage 0 (s=0, w=1): load x directly from gmem ----
    {
        float2 a0, a1, a2, a3;
        if (kind == 0) {
            a0 = make_float2(xb[3 * i],           xb[3 * i + 1]);
            a1 = make_float2(xb[3 * (i + 256)],   xb[3 * (i + 256) + 1]);
            a2 = make_float2(xb[3 * (i + 512)],   xb[3 * (i + 512) + 1]);
            a3 = make_float2(xb[3 * (i + 768)],   xb[3 * (i + 768) + 1]);
        } else {
            a0 = make_float2(xb[3 * i + 2],         0.0f);
            a1 = make_float2(xb[3 * (i + 256) + 2], 0.0f);
            a2 = make_float2(xb[3 * (i + 512) + 2], 0.0f);
            a3 = make_float2(xb[3 * (i + 768) + 2], 0.0f);
        }
        float2 t02p = make_float2(a0.x + a2.x, a0.y + a2.y);
        float2 t02m = make_float2(a0.x - a2.x, a0.y - a2.y);
        float2 t13p = make_float2(a1.x + a3.x, a1.y + a3.y);
        float2 t13m = make_float2(a1.x - a3.x, a1.y - a3.y);
        const int d = i << 2;
        mA[d]     = make_float2(t02p.x + t13p.x, t02p.y + t13p.y);
        mA[d + 1] = make_float2(t02m.x + t13m.y, t02m.y - t13m.x);
        mA[d + 2] = make_float2(t02p.x - t13p.x, t02p.y - t13p.y);
        mA[d + 3] = make_float2(t02m.x - t13m.y, t02m.y + t13m.x);
    }
    barx(1 + g, 256);

    // ---- forward stages 1..3 (group-local barriers) ----
    {
        float2* src = mA;
        float2* dst = mB;
#pragma unroll
        for (int s = 1; s < 4; s++) {
            const int L = 1 << (2 * s);
            const int q = i & (L - 1);
            const int d = ((i >> (2 * s)) << (2 * s + 2)) | q;
            const float2 w1t = tw[q << (8 - 2 * s)];
            const float2 w2t = make_float2(w1t.x * w1t.x - w1t.y * w1t.y,
                                           2.0f * w1t.x * w1t.y);
            const float2 w3t = cmul(w2t, w1t);

            float2 a0 = src[i];
            float2 a1 = src[i + 256];
            float2 a2 = src[i + 512];
            float2 a3 = src[i + 768];
            float2 b1_ = cmul(a1, w1t);
            float2 b2_ = cmul(a2, w2t);
            float2 b3_ = cmul(a3, w3t);

            float2 t02p = make_float2(a0.x + b2_.x, a0.y + b2_.y);
            float2 t02m = make_float2(a0.x - b2_.x, a0.y - b2_.y);
            float2 t13p = make_float2(b1_.x + b3_.x, b1_.y + b3_.y);
            float2 t13m = make_float2(b1_.x - b3_.x, b1_.y - b3_.y);

            dst[d]         = make_float2(t02p.x + t13p.x, t02p.y + t13p.y);
            dst[d + L]     = make_float2(t02m.x + t13m.y, t02m.y - t13m.x);
            dst[d + 2 * L] = make_float2(t02p.x - t13p.x, t02p.y - t13p.y);
            dst[d + 3 * L] = make_float2(t02m.x - t13m.y, t02m.y + t13m.x);

            float2* tmp = src; src = dst; dst = tmp;
            barx(1 + g, 256);
        }
    }
    // stage-3 output in mB

    // ---- forward stage 4: spectra into mA, then FULL join ----
    {
        const float2 w1t = tw[i];
        const float2 w2t = make_float2(w1t.x * w1t.x - w1t.y * w1t.y,
                                       2.0f * w1t.x * w1t.y);
        const float2 w3t = cmul(w2t, w1t);

        float2 a0 = mB[i];
        float2 a1 = mB[i + 256];
        float2 a2 = mB[i + 512];
        float2 a3 = mB[i + 768];
        float2 b1_ = cmul(a1, w1t);
        float2 b2_ = cmul(a2, w2t);
        float2 b3_ = cmul(a3, w3t);

        float2 t02p = make_float2(a0.x + b2_.x, a0.y + b2_.y);
        float2 t02m = make_float2(a0.x - b2_.x, a0.y - b2_.y);
        float2 t13p = make_float2(b1_.x + b3_.x, b1_.y + b3_.y);
        float2 t13m = make_float2(b1_.x - b3_.x, b1_.y - b3_.y);

        mA[i]       = make_float2(t02p.x + t13p.x, t02p.y + t13p.y);
        mA[i + 256] = make_float2(t02m.x + t13m.y, t02m.y - t13m.x);
        mA[i + 512] = make_float2(t02p.x - t13p.x, t02p.y - t13p.y);
        mA[i + 768] = make_float2(t02m.x - t13m.y, t02m.y + t13m.x);
    }
    __syncthreads();   // full join: 4 spectra in bufA

    // ---- inverse on group 0: u = P_b0 + i*P_b1, stage 0 fused with PS ----
    u64* c2 = (u64*)bufB;          // packed (c_b0[j], c_b1[j]) after stage 4
    if (t < 256) {
        const float2* Z01a = bufA;
        const float2* Z2a  = bufA + 1024;
        const float2* Z01b = bufA + 2048;
        const float2* Z2b  = bufA + 3072;

        float2 u[4];
#pragma unroll
        for (int r = 0; r < 4; r++) {
            int k = t + 256 * r;
            int m = (1024 - k) & 1023;
            float2 za  = Z01a[k], zam = Z01a[m], z2a = Z2a[k];
            float2 zb  = Z01b[k], zbm = Z01b[m], z2b = Z2b[k];
            float P0 = 0.5f * (za.x * za.x + za.y * za.y +
                               zam.x * zam.x + zam.y * zam.y)
                     + (z2a.x * z2a.x + z2a.y * z2a.y);
            float P1 = 0.5f * (zb.x * zb.x + zb.y * zb.y +
                               zbm.x * zbm.x + zbm.y * zbm.y)
                     + (z2b.x * z2b.x + z2b.y * z2b.y);
            u[r] = make_float2(P0, P1);
        }
        float2 t02p = make_float2(u[0].x + u[2].x, u[0].y + u[2].y);
        float2 t02m = make_float2(u[0].x - u[2].x, u[0].y - u[2].y);
        float2 t13p = make_float2(u[1].x + u[3].x, u[1].y + u[3].y);
        float2 t13m = make_float2(u[1].x - u[3].x, u[1].y - u[3].y);
        const int d = t << 2;
        bufB[d]     = make_float2(t02p.x + t13p.x, t02p.y + t13p.y);
        bufB[d + 1] = make_float2(t02m.x + t13m.y, t02m.y - t13m.x);
        bufB[d + 2] = make_float2(t02p.x - t13p.x, t02p.y - t13p.y);
        bufB[d + 3] = make_float2(t02m.x - t13m.y, t02m.y + t13m.x);

        barx(1, 256);

        // inverse stages 1..3
        const float2* tw0 = twg;
        float2* src = bufB;
        float2* dst = bufA;
#pragma unroll
        for (int s = 1; s < 4; s++) {
            const int L = 1 << (2 * s);
            const int q = t & (L - 1);
            const int d2 = ((t >> (2 * s)) << (2 * s + 2)) | q;
            const float2 w1t = tw0[q << (8 - 2 * s)];
            const float2 w2t = make_float2(w1t.x * w1t.x - w1t.y * w1t.y,
                                           2.0f * w1t.x * w1t.y);
            const float2 w3t = cmul(w2t, w1t);

            float2 a0 = src[t];
            float2 a1 = src[t + 256];
            float2 a2 = src[t + 512];
            float2 a3 = src[t + 768];
            float2 b1_ = cmul(a1, w1t);
            float2 b2_ = cmul(a2, w2t);
            float2 b3_ = cmul(a3, w3t);

            float2 t02p2 = make_float2(a0.x + b2_.x, a0.y + b2_.y);
            float2 t02m2 = make_float2(a0.x - b2_.x, a0.y - b2_.y);
            float2 t13p2 = make_float2(b1_.x + b3_.x, b1_.y + b3_.y);
            float2 t13m2 = make_float2(b1_.x - b3_.x, b1_.y - b3_.y);

            dst[d2]         = make_float2(t02p2.x + t13p2.x, t02p2.y + t13p2.y);
            dst[d2 + L]     = make_float2(t02m2.x + t13m2.y, t02m2.y - t13m2.x);
            dst[d2 + 2 * L] = make_float2(t02p2.x - t13p2.x, t02p2.y - t13p2.y);
            dst[d2 + 3 * L] = make_float2(t02m2.x - t13m2.y, t02m2.y + t13m2.x);

            float2* tmp = src; src = dst; dst = tmp;
            barx(1, 256);
        }
        // stage-3 output in bufA

        // inverse stage 4: write packed c directly to smem (Re=c_b0, Im=c_b1)
        {
            const float2 w1t = tw0[t];
            const float2 w2t = make_float2(w1t.x * w1t.x - w1t.y * w1t.y,
                                           2.0f * w1t.x * w1t.y);
            const float2 w3t = cmul(w2t, w1t);

            float2 a0 = bufA[t];
            float2 a1 = bufA[t + 256];
            float2 a2 = bufA[t + 512];
            float2 a3 = bufA[t + 768];
            float2 b1_ = cmul(a1, w1t);
            float2 b2_ = cmul(a2, w2t);
            float2 b3_ = cmul(a3, w3t);

            float2 t02p2 = make_float2(a0.x + b2_.x, a0.y + b2_.y);
            float2 t02m2 = make_float2(a0.x - b2_.x, a0.y - b2_.y);
            float2 t13p2 = make_float2(b1_.x + b3_.x, b1_.y + b3_.y);
            float2 t13m2 = make_float2(b1_.x - b3_.x, b1_.y - b3_.y);

            const float inv = 1.0f / (1024.0f * 1024.0f);
            c2[t] = pk2((t02p2.x + t13p2.x) * inv, (t02p2.y + t13p2.y) * inv);
            c2[t + 256] = pk2((t02m2.x + t13m2.y) * inv,
                              (t02m2.y - t13m2.x) * inv);
            c2[t + 512] = pk2((t02p2.x - t13p2.x) * inv,
                              (t02p2.y - t13p2.y) * inv);
            c2[t + 768] = pk2((t02m2.x - t13m2.y) * inv,
                              (t02m2.y + t13m2.x) * inv);
        }
    }
    __syncthreads();   // c2 ready for all 1024 threads

    // ================= phase 3: gemm1 (W1 streamed from L2) =================
    // thread t: h4 = t&31 (4 h via float4), jc = t>>5 (32 j-chunks of 32)
    u64* part = (u64*)dsm;              // [32][128] u64, overlays bufA
    {
        const int h4 = t & 31;
        const int jc = t >> 5;
        const float4* __restrict__ W1v = (const float4*)W1;

        u64 a0 = 0ull, a1 = 0ull, a2 = 0ull, a3 = 0ull;
#pragma unroll 8
        for (int j = jc * 32; j < jc * 32 + 32; j++) {
            u64 cv = c2[j];
            float4 wv = W1v[(j << 5) + h4];
            a0 = fma2(cv, pk2(wv.x, wv.x), a0);
            a1 = fma2(cv, pk2(wv.y, wv.y), a1);
            a2 = fma2(cv, pk2(wv.z, wv.z), a2);
            a3 = fma2(cv, pk2(wv.w, wv.w), a3);
        }
        part[jc * 128 + h4 * 4 + 0] = a0;
        part[jc * 128 + h4 * 4 + 1] = a1;
        part[jc * 128 + h4 * 4 + 2] = a2;
        part[jc * 128 + h4 * 4 + 3] = a3;
    }
    __syncthreads();

    // reduce 32 j-chunks -> red2[4][128], then h1
    u64*   red2 = (u64*)(dsm + 65536);          // 4KB, overlays twg
    float* h1s  = (float*)(dsm + 65536 + 4096); // [2][128]
    if (t < 512) {
        const int h = t & 127, q = t >> 7;
        u64 s0 = 0ull, s1 = 0ull;
#pragma unroll
        for (int jc = q * 8; jc < q * 8 + 8; jc += 2) {
            s0 = add2(s0, part[jc * 128 + h]);
            s1 = add2(s1, part[(jc + 1) * 128 + h]);
        }
        red2[q * 128 + h] = add2(s0, s1);
    }
    __syncthreads();

    if (t < 128) {
        u64 v = add2(add2(red2[t], red2[128 + t]),
                     add2(red2[256 + t], red2[384 + t]));
        float va, vb;
        upk2(v, va, vb);
        float bb = b1[t];
        h1s[t]       = celu1(va + bb);
        h1s[128 + t] = celu1(vb + bb);
    }
    __syncthreads();

    // ================= phase 4: mlp23 =================
    u64* s2u = (u64*)(dsm + 32768 + 8192);   // [8][128], after c2 in bufB
    u64* rb  = (u64*)(dsm + 32768 + 16384);  // [128]
    {
        const int h = t & 127, kc = t >> 7;
        float a0 = 0.f, a1 = 0.f;
#pragma unroll
        for (int k = kc * 16; k < kc * 16 + 16; k++) {
            float w = W2[k * HID + h];
            a0 += h1s[k] * w;
            a1 += h1s[128 + k] * w;
        }
        s2u[kc * 128 + h] = pk2(a0, a1);
    }
    __syncthreads();

    if (t < 128) {
        u64 v = 0ull;
#pragma unroll
        for (int q = 0; q < 8; q += 2)
            v = add2(v, add2(s2u[q * 128 + t], s2u[(q + 1) * 128 + t]));
        float va, vb;
        upk2(v, va, vb);
        float bb = b2[t];
        float w3 = W3[t];
        rb[t] = pk2(celu1(va + bb) * w3, celu1(vb + bb) * w3);
    }
    __syncthreads();
#pragma unroll
    for (int o = 64; o > 0; o >>= 1) {
        if (t < o) rb[t] = add2(rb[t], rb[t + o]);
        __syncthreads();
    }
    if (t == 0) {
        float ya, yb;
        upk2(rb[0], ya, yb);
        float bb = b3[0];
        out[B0]     = ya + bb;
        out[B0 + 1] = yb + bb;
    }
}

// ---------------------------------------------------------------------------
extern "C" void kernel_launch(void* const* d_in, const int* in_sizes, int n_in,
                              void* d_out, int out_size) {
    const float* x  = (const float*)d_in[0];
    const float* W1 = (const float*)d_in[1];
    const float* b1 = (const float*)d_in[2];
    const float* W2 = (const float*)d_in[3];
    const float* b2 = (const float*)d_in[4];
    const float* W3 = (const float*)d_in[5];
    const float* b3 = (const float*)d_in[6];
    float* out = (float*)d_out;

    static int configured = 0;
    if (!configured) {
        cudaFuncSetAttribute(fused_all,
                             cudaFuncAttributeMaxDynamicSharedMemorySize,
                             SMEM_BYTES);
        configured = 1;
    }

    fused_all<<<BATCH / 2, 1024, SMEM_BYTES>>>(x, W1, b1, W2, b2, W3, b3, out);
}

// round 16
// speedup vs baseline: 1.1598x; 1.0173x over previous
#include <cuda_runtime.h>
#include <cuda_bf16.h>

// ---------------------------------------------------------------------------
// MLP_TI_Gram, single self-contained kernel. 64 CTAs x 512 threads, one batch
// PAIR per CTA, zero cross-CTA communication.
// SIMD-f32x2 FFT: both batches' signals packed lane-wise (R=(re0,re1),
// I=(im0,im1)); all butterfly arithmetic is component-wise f32x2 since the
// two lanes share twiddles. Power spectrum is lane-wise too, and the packed
// pair (P_b0,P_b1) IS the inverse input u = P_b0 + i*P_b1 (both real-even =>
// Re(FFT(u)) = N^2 c_b0, Im = N^2 c_b1).
//   phase 1: 2 SIMD forward FFTs (ch01-pair, ch2-pair), 256 thr each.
//   phase 2: packed inverse (256 thr), c kept in smem.
//   phase 3: gemm1 (W1 streamed from L2), phase 4: mlp23 -> out.
// ---------------------------------------------------------------------------

#define BATCH 128
#define NSEQ  1024
#define HID   128

typedef unsigned long long u64;

// ---- f32x2 packed helpers (Blackwell, PTX-only) ---------------------------
__device__ __forceinline__ u64 pk2(float lo, float hi) {
    u64 r;
    asm("mov.b64 %0, {%1,%2};" : "=l"(r) : "f"(lo), "f"(hi));
    return r;
}
__device__ __forceinline__ void upk2(u64 v, float& lo, float& hi) {
    asm("mov.b64 {%0,%1}, %2;" : "=f"(lo), "=f"(hi) : "l"(v));
}
__device__ __forceinline__ u64 fma2(u64 a, u64 b, u64 c) {
    u64 d;
    asm("fma.rn.f32x2 %0, %1, %2, %3;" : "=l"(d) : "l"(a), "l"(b), "l"(c));
    return d;
}
__device__ __forceinline__ u64 add2(u64 a, u64 b) {
    u64 d;
    asm("add.rn.f32x2 %0, %1, %2;" : "=l"(d) : "l"(a), "l"(b));
    return d;
}
__device__ __forceinline__ u64 mul2(u64 a, u64 b) {
    u64 d;
    asm("mul.rn.f32x2 %0, %1, %2;" : "=l"(d) : "l"(a), "l"(b));
    return d;
}

__device__ __forceinline__ float celu1(float v) {
    return v > 0.0f ? v : expm1f(v);
}
__device__ __forceinline__ float2 cmul(float2 a, float2 b) {
    return make_float2(a.x * b.x - a.y * b.y, a.x * b.y + a.y * b.x);
}
__device__ __forceinline__ void barx(int id, int cnt) {
    asm volatile("bar.sync %0, %1;" :: "r"(id), "r"(cnt) : "memory");
}

// SIMD complex multiply: (Rb,Ib) = (Ra,Ia) * w, both lanes by scalar w.
// wx2=(wx,wx), wy2=(wy,wy), wyn2=(-wy,-wy).
#define SCMUL(Rb, Ib, Ra, Ia, wx2, wy2, wyn2) do { \
    (Rb) = fma2((Ia), (wyn2), mul2((Ra), (wx2))); \
    (Ib) = fma2((Ia), (wx2),  mul2((Ra), (wy2))); \
} while (0)

// ---------------------------------------------------------------------------
// Dynamic smem map (u64 units):
//   G0: RA 0..1023 | IA 1024..2047 | RB 2048..3071 | IB 3072..4095
//   G1: RA 4096..  | IA 5120..     | RB 6144..     | IB 7168..8191
//   tw float2[768] at u64 8192..8959  (6KB)
// Overlays (after their sources are dead):
//   inverse ping-pong: bufX = (float2*)(G0 RB), bufY = (float2*)(G0 IB)
//   c2 (packed c pair)    -> 6144..7167   (G1 RB)
//   part[16][128]         -> 0..2047      (G0 RA/IA)
//   red2[4][128]          -> 4096..4607   (G1 RA)
//   h1s float[256]        -> 4608..4639
//   s2u[4][128]           -> 4864..5375
//   rb[128]               -> 5504..5631
// ---------------------------------------------------------------------------
#define SMEM_BYTES (8960 * 8)

__global__ __launch_bounds__(512, 1)
void fused_all(const float* __restrict__ x,
               const float* __restrict__ W1, const float* __restrict__ b1,
               const float* __restrict__ W2, const float* __restrict__ b2,
               const float* __restrict__ W3, const float* __restrict__ b3,
               float* __restrict__ out) {
    extern __shared__ char dsm_raw[];
    u64* sm = (u64*)dsm_raw;
    float2* tw = (float2*)(sm + 8192);

    const int t = threadIdx.x;
    const int g = t >> 8;               // SIMD group: 0 = ch01-pair, 1 = ch2-pair
    const int i = t & 255;

    const int B0 = blockIdx.x * 2;
    const float* __restrict__ xb0 = x + (size_t)B0 * NSEQ * 3;
    const float* __restrict__ xb1 = xb0 + NSEQ * 3;

    const u64 M1   = pk2(-1.0f, -1.0f);
    const u64 HALF = pk2(0.5f, 0.5f);
#define sub2(a, b) fma2((b), M1, (a))

    // twiddle table: tw[m] = exp(-2*pi*i*m/1024), m in [0,768)
    for (int m = t; m < 768; m += 512) {
        float s_, c_;
        sincospif(-(float)m * (1.0f / 512.0f), &s_, &c_);
        tw[m] = make_float2(c_, s_);
    }
    __syncthreads();

    u64* mRA = sm + g * 4096;
    u64* mIA = mRA + 1024;
    u64* mRB = mRA + 2048;
    u64* mIB = mRA + 3072;

    // ---- forward stage 0 (w=1): load x pair directly from gmem ----
    {
        u64 Ra[4], Ia[4];
#pragma unroll
        for (int r = 0; r < 4; r++) {
            int j3 = 3 * (i + 256 * r);
            if (g == 0) {
                Ra[r] = pk2(xb0[j3],     xb1[j3]);
                Ia[r] = pk2(xb0[j3 + 1], xb1[j3 + 1]);
            } else {
                Ra[r] = pk2(xb0[j3 + 2], xb1[j3 + 2]);
                Ia[r] = 0ull;
            }
        }
        u64 t02pR = add2(Ra[0], Ra[2]), t02pI = add2(Ia[0], Ia[2]);
        u64 t02mR = sub2(Ra[0], Ra[2]), t02mI = sub2(Ia[0], Ia[2]);
        u64 t13pR = add2(Ra[1], Ra[3]), t13pI = add2(Ia[1], Ia[3]);
        u64 t13mR = sub2(Ra[1], Ra[3]), t13mI = sub2(Ia[1], Ia[3]);
        const int d = i << 2;
        mRA[d]     = add2(t02pR, t13pR);  mIA[d]     = add2(t02pI, t13pI);
        mRA[d + 1] = add2(t02mR, t13mI);  mIA[d + 1] = sub2(t02mI, t13mR);
        mRA[d + 2] = sub2(t02pR, t13pR);  mIA[d + 2] = sub2(t02pI, t13pI);
        mRA[d + 3] = sub2(t02mR, t13mI);  mIA[d + 3] = add2(t02mI, t13mR);
    }
    barx(1 + g, 256);

    // ---- forward stages 1..3 (group-local barriers) ----
    {
        u64 *sR = mRA, *sI = mIA, *dR = mRB, *dI = mIB;
#pragma unroll
        for (int s = 1; s < 4; s++) {
            const int L = 1 << (2 * s);
            const int q = i & (L - 1);
            const int d = ((i >> (2 * s)) << (2 * s + 2)) | q;
            const int mi = q << (8 - 2 * s);
            const float2 w1 = tw[mi];
            const float2 w2 = tw[2 * mi];
            const float2 w3 = tw[3 * mi];
            const u64 w1x = pk2(w1.x, w1.x), w1y = pk2(w1.y, w1.y), w1n = pk2(-w1.y, -w1.y);
            const u64 w2x = pk2(w2.x, w2.x), w2y = pk2(w2.y, w2.y), w2n = pk2(-w2.y, -w2.y);
            const u64 w3x = pk2(w3.x, w3.x), w3y = pk2(w3.y, w3.y), w3n = pk2(-w3.y, -w3.y);

            u64 Ra0 = sR[i],       Ia0 = sI[i];
            u64 Ra1 = sR[i + 256], Ia1 = sI[i + 256];
            u64 Ra2 = sR[i + 512], Ia2 = sI[i + 512];
            u64 Ra3 = sR[i + 768], Ia3 = sI[i + 768];
            u64 Rb1, Ib1, Rb2, Ib2, Rb3, Ib3;
            SCMUL(Rb1, Ib1, Ra1, Ia1, w1x, w1y, w1n);
            SCMUL(Rb2, Ib2, Ra2, Ia2, w2x, w2y, w2n);
            SCMUL(Rb3, Ib3, Ra3, Ia3, w3x, w3y, w3n);

            u64 t02pR = add2(Ra0, Rb2), t02pI = add2(Ia0, Ib2);
            u64 t02mR = sub2(Ra0, Rb2), t02mI = sub2(Ia0, Ib2);
            u64 t13pR = add2(Rb1, Rb3), t13pI = add2(Ib1, Ib3);
            u64 t13mR = sub2(Rb1, Rb3), t13mI = sub2(Ib1, Ib3);

            dR[d]         = add2(t02pR, t13pR);  dI[d]         = add2(t02pI, t13pI);
            dR[d + L]     = add2(t02mR, t13mI);  dI[d + L]     = sub2(t02mI, t13mR);
            dR[d + 2 * L] = sub2(t02pR, t13pR);  dI[d + 2 * L] = sub2(t02pI, t13pI);
            dR[d + 3 * L] = sub2(t02mR, t13mI);  dI[d + 3 * L] = add2(t02mI, t13mR);

            u64* tmp;
            tmp = sR; sR = dR; dR = tmp;
            tmp = sI; sI = dI; dI = tmp;
            barx(1 + g, 256);
        }
    }
    // stage-3 output in B arrays

    // ---- forward stage 4: spectra into A arrays ----
    {
        const float2 w1 = tw[i];
        const float2 w2 = tw[2 * i];
        const float2 w3 = tw[3 * i];
        const u64 w1x = pk2(w1.x, w1.x), w1y = pk2(w1.y, w1.y), w1n = pk2(-w1.y, -w1.y);
        const u64 w2x = pk2(w2.x, w2.x), w2y = pk2(w2.y, w2.y), w2n = pk2(-w2.y, -w2.y);
        const u64 w3x = pk2(w3.x, w3.x), w3y = pk2(w3.y, w3.y), w3n = pk2(-w3.y, -w3.y);

        u64 Ra0 = mRB[i],       Ia0 = mIB[i];
        u64 Ra1 = mRB[i + 256], Ia1 = mIB[i + 256];
        u64 Ra2 = mRB[i + 512], Ia2 = mIB[i + 512];
        u64 Ra3 = mRB[i + 768], Ia3 = mIB[i + 768];
        u64 Rb1, Ib1, Rb2, Ib2, Rb3, Ib3;
        SCMUL(Rb1, Ib1, Ra1, Ia1, w1x, w1y, w1n);
        SCMUL(Rb2, Ib2, Ra2, Ia2, w2x, w2y, w2n);
        SCMUL(Rb3, Ib3, Ra3, Ia3, w3x, w3y, w3n);

        u64 t02pR = add2(Ra0, Rb2), t02pI = add2(Ia0, Ib2);
        u64 t02mR = sub2(Ra0, Rb2), t02mI = sub2(Ia0, Ib2);
        u64 t13pR = add2(Rb1, Rb3), t13pI = add2(Ib1, Ib3);
        u64 t13mR = sub2(Rb1, Rb3), t13mI = sub2(Ib1, Ib3);

        mRA[i]       = add2(t02pR, t13pR);  mIA[i]       = add2(t02pI, t13pI);
        mRA[i + 256] = add2(t02mR, t13mI);  mIA[i + 256] = sub2(t02mI, t13mR);
        mRA[i + 512] = sub2(t02pR, t13pR);  mIA[i + 512] = sub2(t02pI, t13pI);
        mRA[i + 768] = sub2(t02mR, t13mI);  mIA[i + 768] = add2(t02mI, t13mR);
    }
    __syncthreads();   // full join: spectra of both pairs in A arrays

    // ---- inverse: u = P_b0 + i*P_b1 (SIMD PS), stage 0 fused ----
    u64* c2 = sm + 6144;                 // packed (c_b0, c_b1)
    float2* bufX = (float2*)(sm + 2048); // G0 RB region
    float2* bufY = (float2*)(sm + 3072); // G0 IB region
    if (t < 256) {
        const u64* R01 = sm;
        const u64* I01 = sm + 1024;
        const u64* R2h = sm + 4096;
        const u64* I2h = sm + 5120;

        float2 u[4];
#pragma unroll
        for (int r = 0; r < 4; r++) {
            int k = t + 256 * r;
            int m = (1024 - k) & 1023;
            u64 s1 = fma2(R01[k], R01[k], mul2(I01[k], I01[k]));
            s1 = add2(s1, fma2(R01[m], R01[m], mul2(I01[m], I01[m])));
            s1 = mul2(s1, HALF);
            s1 = add2(s1, fma2(R2h[k], R2h[k], mul2(I2h[k], I2h[k])));
            float P0, P1;
            upk2(s1, P0, P1);
            u[r] = make_float2(P0, P1);   // complex u = P_b0 + i*P_b1
        }
        float2 t02p = make_float2(u[0].x + u[2].x, u[0].y + u[2].y);
        float2 t02m = make_float2(u[0].x - u[2].x, u[0].y - u[2].y);
        float2 t13p = make_float2(u[1].x + u[3].x, u[1].y + u[3].y);
        float2 t13m = make_float2(u[1].x - u[3].x, u[1].y - u[3].y);
        const int d = t << 2;
        bufX[d]     = make_float2(t02p.x + t13p.x, t02p.y + t13p.y);
        bufX[d + 1] = make_float2(t02m.x + t13m.y, t02m.y - t13m.x);
        bufX[d + 2] = make_float2(t02p.x - t13p.x, t02p.y - t13p.y);
        bufX[d + 3] = make_float2(t02m.x - t13m.y, t02m.y + t13m.x);

        barx(1, 256);

        // inverse stages 1..3
        float2* src = bufX;
        float2* dst = bufY;
#pragma unroll
        for (int s = 1; s < 4; s++) {
            const int L = 1 << (2 * s);
            const int q = t & (L - 1);
            const int d2 = ((t >> (2 * s)) << (2 * s + 2)) | q;
            const int mi = q << (8 - 2 * s);
            const float2 w1t = tw[mi];
            const float2 w2t = tw[2 * mi];
            const float2 w3t = tw[3 * mi];

            float2 a0 = src[t];
            float2 a1 = src[t + 256];
            float2 a2 = src[t + 512];
            float2 a3 = src[t + 768];
            float2 b1_ = cmul(a1, w1t);
            float2 b2_ = cmul(a2, w2t);
            float2 b3_ = cmul(a3, w3t);

            float2 t02p2 = make_float2(a0.x + b2_.x, a0.y + b2_.y);
            float2 t02m2 = make_float2(a0.x - b2_.x, a0.y - b2_.y);
            float2 t13p2 = make_float2(b1_.x + b3_.x, b1_.y + b3_.y);
            float2 t13m2 = make_float2(b1_.x - b3_.x, b1_.y - b3_.y);

            dst[d2]         = make_float2(t02p2.x + t13p2.x, t02p2.y + t13p2.y);
            dst[d2 + L]     = make_float2(t02m2.x + t13m2.y, t02m2.y - t13m2.x);
            dst[d2 + 2 * L] = make_float2(t02p2.x - t13p2.x, t02p2.y - t13p2.y);
            dst[d2 + 3 * L] = make_float2(t02m2.x - t13m2.y, t02m2.y + t13m2.x);

            float2* tmp = src; src = dst; dst = tmp;
            barx(1, 256);
        }
        // stage-3 output in bufY

        // inverse stage 4: packed c straight to smem (Re=c_b0, Im=c_b1)
        {
            const float2 w1t = tw[t];
            const float2 w2t = tw[2 * t];
            const float2 w3t = tw[3 * t];

            float2 a0 = bufY[t];
            float2 a1 = bufY[t + 256];
            float2 a2 = bufY[t + 512];
            float2 a3 = bufY[t + 768];
            float2 b1_ = cmul(a1, w1t);
            float2 b2_ = cmul(a2, w2t);
            float2 b3_ = cmul(a3, w3t);

            float2 t02p2 = make_float2(a0.x + b2_.x, a0.y + b2_.y);
            float2 t02m2 = make_float2(a0.x - b2_.x, a0.y - b2_.y);
            float2 t13p2 = make_float2(b1_.x + b3_.x, b1_.y + b3_.y);
            float2 t13m2 = make_float2(b1_.x - b3_.x, b1_.y - b3_.y);

            const float inv = 1.0f / (1024.0f * 1024.0f);
            c2[t] = pk2((t02p2.x + t13p2.x) * inv, (t02p2.y + t13p2.y) * inv);
            c2[t + 256] = pk2((t02m2.x + t13m2.y) * inv,
                              (t02m2.y - t13m2.x) * inv);
            c2[t + 512] = pk2((t02p2.x - t13p2.x) * inv,
                              (t02p2.y - t13p2.y) * inv);
            c2[t + 768] = pk2((t02m2.x - t13m2.y) * inv,
                              (t02m2.y + t13m2.x) * inv);
        }
    }
    __syncthreads();   // c2 ready

    // ================= phase 3: gemm1 (W1 streamed from L2) =================
    u64* part = sm;                      // [16][128]
    {
        const int h4 = t & 31;
        const int jc = t >> 5;           // [0,16), 64 j each
        const float4* __restrict__ W1v = (const float4*)W1;

        u64 a0 = 0ull, a1 = 0ull, a2 = 0ull, a3 = 0ull;
#pragma unroll 8
        for (int j = jc * 64; j < jc * 64 + 64; j++) {
            u64 cv = c2[j];
            float4 wv = W1v[(j << 5) + h4];
            a0 = fma2(cv, pk2(wv.x, wv.x), a0);
            a1 = fma2(cv, pk2(wv.y, wv.y), a1);
            a2 = fma2(cv, pk2(wv.z, wv.z), a2);
            a3 = fma2(cv, pk2(wv.w, wv.w), a3);
        }
        part[jc * 128 + h4 * 4 + 0] = a0;
        part[jc * 128 + h4 * 4 + 1] = a1;
        part[jc * 128 + h4 * 4 + 2] = a2;
        part[jc * 128 + h4 * 4 + 3] = a3;
    }
    __syncthreads();

    u64*   red2 = sm + 4096;             // [4][128]
    float* h1s  = (float*)(sm + 4608);   // [2][128]
    {
        const int h = t & 127, q = t >> 7;
        u64 s0 = 0ull, s1 = 0ull;
#pragma unroll
        for (int jc = q * 4; jc < q * 4 + 4; jc += 2) {
            s0 = add2(s0, part[jc * 128 + h]);
            s1 = add2(s1, part[(jc + 1) * 128 + h]);
        }
        red2[q * 128 + h] = add2(s0, s1);
    }
    __syncthreads();

    if (t < 128) {
        u64 v = add2(add2(red2[t], red2[128 + t]),
                     add2(red2[256 + t], red2[384 + t]));
        float va, vb;
        upk2(v, va, vb);
        float bb = b1[t];
        h1s[t]       = celu1(va + bb);
        h1s[128 + t] = celu1(vb + bb);
    }
    __syncthreads();

    // ================= phase 4: mlp23 =================
    u64* s2u = sm + 4864;                // [4][128]
    u64* rb  = sm + 5504;                // [128]
    {
        const int h = t & 127, kc = t >> 7;
        float a0 = 0.f, a1 = 0.f;
#pragma unroll
        for (int k = kc * 32; k < kc * 32 + 32; k++) {
            float w = W2[k * HID + h];
            a0 += h1s[k] * w;
            a1 += h1s[128 + k] * w;
        }
        s2u[kc * 128 + h] = pk2(a0, a1);
    }
    __syncthreads();

    if (t < 128) {
        u64 v = add2(add2(s2u[t], s2u[128 + t]),
                     add2(s2u[256 + t], s2u[384 + t]));
        float va, vb;
        upk2(v, va, vb);
        float bb = b2[t];
        float w3 = W3[t];
        rb[t] = pk2(celu1(va + bb) * w3, celu1(vb + bb) * w3);
    }
    __syncthreads();
#pragma unroll
    for (int o = 64; o > 0; o >>= 1) {
        if (t < o) rb[t] = add2(rb[t], rb[t + o]);
        __syncthreads();
    }
    if (t == 0) {
        float ya, yb;
        upk2(rb[0], ya, yb);
        float bb = b3[0];
        out[B0]     = ya + bb;
        out[B0 + 1] = yb + bb;
    }
#undef sub2
}

// ---------------------------------------------------------------------------
extern "C" void kernel_launch(void* const* d_in, const int* in_sizes, int n_in,
                              void* d_out, int out_size) {
    const float* x  = (const float*)d_in[0];
    const float* W1 = (const float*)d_in[1];
    const float* b1 = (const float*)d_in[2];
    const float* W2 = (const float*)d_in[3];
    const float* b2 = (const float*)d_in[4];
    const float* W3 = (const float*)d_in[5];
    const float* b3 = (const float*)d_in[6];
    float* out = (float*)d_out;

    static int configured = 0;
    if (!configured) {
        cudaFuncSetAttribute(fused_all,
                             cudaFuncAttributeMaxDynamicSharedMemorySize,
                             SMEM_BYTES);
        configured = 1;
    }

    fused_all<<<BATCH / 2, 512, SMEM_BYTES>>>(x, W1, b1, W2, b2, W3, b3, out);
}